// round 4
// baseline (speedup 1.0000x reference)
#include <cuda_runtime.h>
#include <cuda_fp16.h>
#include <mma.h>

using namespace nvcuda;

#define T_ 4
#define B_ 32
#define C_ 384
#define N_ 256
#define HEADS_ 8
#define DH_ 48
#define MQK 768   // q rows [0,384) and k rows [384,768) stacked

static constexpr int BCN  = B_ * C_ * N_;        // 3,145,728
static constexpr int TBCN = T_ * BCN;            // 12,582,912

// ---------------- scratch (static device memory; no cudaMalloc allowed) ----
__device__ __half g_s[TBCN];                          // LIF(x) spikes, binary
__device__ float  g_qk[(size_t)T_ * B_ * MQK * N_];   // BN(conv(s)) for q&k
__device__ __half g_y[TBCN];                          // attn*k, binary
__device__ __half g_Wqk_hi[MQK * C_];
__device__ __half g_Wqk_lo[MQK * C_];
__device__ __half g_Wp_hi[C_ * C_];
__device__ __half g_Wp_lo[C_ * C_];
__device__ float  g_bias_qk[MQK];
__device__ float  g_bias_p[C_];

// ---------------- K0: fold BN into weights, split fp32 -> fp16 hi + lo -----
// fp16 split carries ~22 mantissa bits: |w - hi - lo| <= 2^-22 |w|, i.e.
// fp32-level accuracy through the tensor-core path (binary activations make
// products exact; HMMA accumulates in fp32).
__global__ void prep_weights(
    const float* __restrict__ qw, const float* __restrict__ qg, const float* __restrict__ qb,
    const float* __restrict__ qm, const float* __restrict__ qv,
    const float* __restrict__ kw, const float* __restrict__ kg, const float* __restrict__ kb,
    const float* __restrict__ km, const float* __restrict__ kv,
    const float* __restrict__ pw, const float* __restrict__ pbias, const float* __restrict__ pg,
    const float* __restrict__ pbeta, const float* __restrict__ pm, const float* __restrict__ pv)
{
    int idx = blockIdx.x * blockDim.x + threadIdx.x;
    if (idx < MQK * C_) {
        int d = idx / C_, c = idx % C_;
        float w, inv;
        if (d < C_) {
            inv = qg[d] / sqrtf(qv[d] + 1e-5f);
            w = qw[d * C_ + c] * inv;
        } else {
            int dd = d - C_;
            inv = kg[dd] / sqrtf(kv[dd] + 1e-5f);
            w = kw[dd * C_ + c] * inv;
        }
        __half hi = __float2half(w);
        g_Wqk_hi[idx] = hi;
        g_Wqk_lo[idx] = __float2half(w - __half2float(hi));
    }
    if (idx < C_ * C_) {
        int d = idx / C_;
        float inv = pg[d] / sqrtf(pv[d] + 1e-5f);
        float w = pw[idx] * inv;
        __half hi = __float2half(w);
        g_Wp_hi[idx] = hi;
        g_Wp_lo[idx] = __float2half(w - __half2float(hi));
    }
    if (idx < MQK) {
        float inv, bias;
        if (idx < C_) {
            inv = qg[idx] / sqrtf(qv[idx] + 1e-5f);
            bias = qb[idx] - qm[idx] * inv;
        } else {
            int d = idx - C_;
            inv = kg[d] / sqrtf(kv[d] + 1e-5f);
            bias = kb[d] - km[d] * inv;
        }
        g_bias_qk[idx] = bias;
    }
    if (idx < C_) {
        float inv = pg[idx] / sqrtf(pv[idx] + 1e-5f);
        g_bias_p[idx] = pbias[idx] * inv + pbeta[idx] - pm[idx] * inv;
    }
}

// ---------------- K1: multi-step LIF over raw input -> binary spikes -------
__global__ void lif_input(const float* __restrict__ x, __half* __restrict__ s)
{
    int j = blockIdx.x * blockDim.x + threadIdx.x;
    if (j >= BCN) return;
    float v = 0.0f;
#pragma unroll
    for (int t = 0; t < T_; ++t) {
        v = 0.5f * v + x[t * BCN + j];
        if (v >= 1.0f) {
            s[t * BCN + j] = __float2half(1.0f);
            v = 0.0f;
        } else {
            s[t * BCN + j] = __float2half(0.0f);
        }
    }
}

// ---------------- K2/K4: batched split-precision fp16 GEMM -----------------
// Out[z] = (A_hi + A_lo) @ B[z] + bias, fp32 accumulate/output.
// A: M x K row-major (shared across batch). B[z]: K x N_ row-major.
#define BM 128
#define BN 128
#define BK 32
#define SA_STRIDE (BK + 8)   // 40 (multiple of 8 for wmma ldm)
#define SB_STRIDE (BN + 8)   // 136

__global__ __launch_bounds__(256) void gemm_split(
    const __half* __restrict__ A_hi,
    const __half* __restrict__ A_lo,
    const __half* __restrict__ Bmat,
    const float* __restrict__ bias,
    float* __restrict__ Out,
    int M, int K)
{
    extern __shared__ char smem[];
    __half* sA_hi = (__half*)smem;                    // 128*40*2 = 10240 B
    __half* sA_lo = sA_hi + BM * SA_STRIDE;           // 10240 B
    __half* sB    = sA_lo + BM * SA_STRIDE;           // 32*136*2 = 8704 B
    float* stage = (float*)smem;                      // epilogue reuse: 64 KB

    const int z     = blockIdx.z;
    const int tileM = blockIdx.y * BM;
    const int tileN = blockIdx.x * BN;
    const __half* Bz = Bmat + (size_t)z * K * N_;
    float* Oz = Out + (size_t)z * M * N_;

    const int tid  = threadIdx.x;
    const int warp = tid >> 5;
    const int wm   = warp & 1;   // 2 warps along M (64 rows each)
    const int wn   = warp >> 1;  // 4 warps along N (32 cols each)

    wmma::fragment<wmma::accumulator, 16, 16, 16, float> c[4][2];
#pragma unroll
    for (int i = 0; i < 4; i++)
#pragma unroll
        for (int j = 0; j < 2; j++) wmma::fill_fragment(c[i][j], 0.0f);

    for (int k0 = 0; k0 < K; k0 += BK) {
        // load A_hi / A_lo tiles: 128x32 each -> 512 uint4 vectors each
#pragma unroll
        for (int i = 0; i < 2; i++) {
            int v = tid + i * 256;
            int r  = v >> 2;
            int ck = (v & 3) << 3;
            *(uint4*)(sA_hi + r * SA_STRIDE + ck) =
                *(const uint4*)(A_hi + (size_t)(tileM + r) * K + k0 + ck);
            *(uint4*)(sA_lo + r * SA_STRIDE + ck) =
                *(const uint4*)(A_lo + (size_t)(tileM + r) * K + k0 + ck);
        }
        // load B tile: 32x128 -> 512 uint4 vectors
#pragma unroll
        for (int i = 0; i < 2; i++) {
            int v = tid + i * 256;
            int r  = v >> 4;
            int cn = (v & 15) << 3;
            *(uint4*)(sB + r * SB_STRIDE + cn) =
                *(const uint4*)(Bz + (size_t)(k0 + r) * N_ + tileN + cn);
        }
        __syncthreads();

#pragma unroll
        for (int kk = 0; kk < 2; ++kk) {
            wmma::fragment<wmma::matrix_b, 16, 16, 16, __half, wmma::row_major> bfr[2];
#pragma unroll
            for (int j = 0; j < 2; j++)
                wmma::load_matrix_sync(bfr[j], sB + kk * 16 * SB_STRIDE + wn * 32 + j * 16, SB_STRIDE);
            wmma::fragment<wmma::matrix_a, 16, 16, 16, __half, wmma::row_major> afr;
#pragma unroll
            for (int i = 0; i < 4; i++) {
                wmma::load_matrix_sync(afr, sA_hi + (wm * 64 + i * 16) * SA_STRIDE + kk * 16, SA_STRIDE);
#pragma unroll
                for (int j = 0; j < 2; j++) wmma::mma_sync(c[i][j], afr, bfr[j], c[i][j]);
                wmma::load_matrix_sync(afr, sA_lo + (wm * 64 + i * 16) * SA_STRIDE + kk * 16, SA_STRIDE);
#pragma unroll
                for (int j = 0; j < 2; j++) wmma::mma_sync(c[i][j], afr, bfr[j], c[i][j]);
            }
        }
        __syncthreads();
    }

    // epilogue: stage accumulators in smem, add per-row bias, coalesced write
#pragma unroll
    for (int i = 0; i < 4; i++)
#pragma unroll
        for (int j = 0; j < 2; j++)
            wmma::store_matrix_sync(stage + (wm * 64 + i * 16) * BN + wn * 32 + j * 16,
                                    c[i][j], BN, wmma::mem_row_major);
    __syncthreads();
#pragma unroll
    for (int v0 = 0; v0 < 16; ++v0) {
        int v  = tid + v0 * 256;       // 0..4095
        int m  = v >> 5;               // row in tile
        int n4 = (v & 31) << 2;        // col (float4)
        float4 val = *(float4*)(stage + m * BN + n4);
        float bb = bias[tileM + m];
        val.x += bb; val.y += bb; val.z += bb; val.w += bb;
        *(float4*)(Oz + (size_t)(tileM + m) * N_ + tileN + n4) = val;
    }
}

// ---------------- K3: q/k LIF + mems closed form + attn gate + y = attn*k --
// mems per-head channel-sums: S_t = sum_dh q spikes. Closed form:
//   q_sum[0]=2*S0, [1]=S0+S1, [2]=m2+S2 (m2=a*S0+(1-a)*S1),
//   [3]=a*m2+(1-a)*S2+S3;  attn = LIF(q_sum, tau=.5, thr=.5); y = attn*k.
__global__ void spike_attn(const float* __restrict__ qk,
                           const float* __restrict__ alpha_p,
                           __half* __restrict__ y)
{
    int id = blockIdx.x * blockDim.x + threadIdx.x;
    if (id >= B_ * HEADS_ * N_) return;
    const int n  = id & (N_ - 1);
    const int hh = (id >> 8) & (HEADS_ - 1);
    const int b  = id >> 11;
    const float alpha = *alpha_p;
    const int rowq = hh * DH_;

    float S[T_] = {0.f, 0.f, 0.f, 0.f};
    unsigned long long kb[T_] = {0ull, 0ull, 0ull, 0ull};

    for (int dh = 0; dh < DH_; ++dh) {
        float vq = 0.f, vk = 0.f;
#pragma unroll
        for (int t = 0; t < T_; ++t) {
            size_t base = (size_t)(t * B_ + b) * MQK;
            float qv = qk[(base + rowq + dh) * N_ + n];
            vq = 0.5f * vq + qv;
            if (vq >= 1.0f) { S[t] += 1.0f; vq = 0.f; }
            float kv = qk[(base + C_ + rowq + dh) * N_ + n];
            vk = 0.5f * vk + kv;
            if (vk >= 1.0f) { kb[t] |= (1ull << dh); vk = 0.f; }
        }
    }

    const float om = 1.0f - alpha;
    float m2 = alpha * S[0] + om * S[1];
    float qs[T_];
    qs[0] = S[0] + S[0];
    qs[1] = S[0] + S[1];
    qs[2] = m2 + S[2];
    qs[3] = alpha * m2 + om * S[2] + S[3];

    const __half one  = __float2half(1.0f);
    const __half zero = __float2half(0.0f);
    float v = 0.f;
#pragma unroll
    for (int t = 0; t < T_; ++t) {
        v = 0.5f * v + qs[t];
        unsigned long long mask = 0ull;
        if (v >= 0.5f) { mask = kb[t]; v = 0.f; }
        size_t base = ((size_t)(t * B_ + b) * C_ + rowq) * N_ + n;
        for (int dh = 0; dh < DH_; ++dh)
            y[base + (size_t)dh * N_] = ((mask >> dh) & 1ull) ? one : zero;
    }
}

// ---------------- launch ---------------------------------------------------
extern "C" void kernel_launch(void* const* d_in, const int* in_sizes, int n_in,
                              void* d_out, int out_size)
{
    (void)in_sizes; (void)n_in; (void)out_size;
    const float* x       = (const float*)d_in[0];
    const float* q_w     = (const float*)d_in[1];
    const float* q_gamma = (const float*)d_in[2];
    const float* q_beta  = (const float*)d_in[3];
    const float* q_mean  = (const float*)d_in[4];
    const float* q_var   = (const float*)d_in[5];
    const float* k_w     = (const float*)d_in[6];
    const float* k_gamma = (const float*)d_in[7];
    const float* k_beta  = (const float*)d_in[8];
    const float* k_mean  = (const float*)d_in[9];
    const float* k_var   = (const float*)d_in[10];
    const float* proj_w  = (const float*)d_in[11];
    const float* proj_b  = (const float*)d_in[12];
    const float* proj_g  = (const float*)d_in[13];
    const float* proj_be = (const float*)d_in[14];
    const float* proj_m  = (const float*)d_in[15];
    const float* proj_v  = (const float*)d_in[16];
    const float* m_alpha = (const float*)d_in[17];
    float* out = (float*)d_out;

    // device addresses of scratch symbols (no allocation; capture-safe)
    __half *s_p, *y_p, *wqk_hi, *wqk_lo, *wp_hi, *wp_lo;
    float *qk_p, *bias_qk, *bias_p;
    cudaGetSymbolAddress((void**)&s_p,     g_s);
    cudaGetSymbolAddress((void**)&y_p,     g_y);
    cudaGetSymbolAddress((void**)&wqk_hi,  g_Wqk_hi);
    cudaGetSymbolAddress((void**)&wqk_lo,  g_Wqk_lo);
    cudaGetSymbolAddress((void**)&wp_hi,   g_Wp_hi);
    cudaGetSymbolAddress((void**)&wp_lo,   g_Wp_lo);
    cudaGetSymbolAddress((void**)&qk_p,    g_qk);
    cudaGetSymbolAddress((void**)&bias_qk, g_bias_qk);
    cudaGetSymbolAddress((void**)&bias_p,  g_bias_p);

    cudaFuncSetAttribute(gemm_split, cudaFuncAttributeMaxDynamicSharedMemorySize, 65536);

    // K0: weight prep (BN fold + fp16 hi/lo split)
    prep_weights<<<(MQK * C_) / 256, 256>>>(q_w, q_gamma, q_beta, q_mean, q_var,
                                            k_w, k_gamma, k_beta, k_mean, k_var,
                                            proj_w, proj_b, proj_g, proj_be, proj_m, proj_v);
    // K1: LIF(x) -> s
    lif_input<<<BCN / 256, 256>>>(x, s_p);
    // K2: qk_bn = [Wq';Wk'] @ s + bias  (split fp16, fp32 acc)
    gemm_split<<<dim3(N_ / BN, MQK / BM, T_ * B_), 256, 65536>>>(
        wqk_hi, wqk_lo, s_p, bias_qk, qk_p, MQK, C_);
    // K3: q/k LIF + mems + attn gate -> y (binary)
    spike_attn<<<(B_ * HEADS_ * N_) / 256, 256>>>(qk_p, m_alpha, y_p);
    // K4: out = Wp' @ y + bias_p
    gemm_split<<<dim3(N_ / BN, C_ / BM, T_ * B_), 256, 65536>>>(
        wp_hi, wp_lo, y_p, bias_p, out, C_, C_);
}

// round 5
// speedup vs baseline: 1.0073x; 1.0073x over previous
#include <cuda_runtime.h>
#include <cuda_fp16.h>
#include <mma.h>

using namespace nvcuda;

#define T_ 4
#define B_ 32
#define C_ 384
#define N_ 256
#define HEADS_ 8
#define DH_ 48
#define MQK 768   // q rows [0,384) and k rows [384,768) stacked
#define K_ 384    // GEMM inner dim (both GEMMs)

static constexpr int BCN  = B_ * C_ * N_;        // 3,145,728
static constexpr int TBCN = T_ * BCN;            // 12,582,912

// ---------------- scratch (static device memory; no cudaMalloc allowed) ----
__device__ __half g_s[TBCN];                          // LIF(x) spikes, binary
__device__ float  g_qk[(size_t)T_ * B_ * MQK * N_];   // BN(conv(s)) for q&k
__device__ __half g_y[TBCN];                          // attn*k, binary
__device__ __half g_Wqk_hi[MQK * C_];
__device__ __half g_Wqk_lo[MQK * C_];
__device__ __half g_Wp_hi[C_ * C_];
__device__ __half g_Wp_lo[C_ * C_];
__device__ float  g_bias_qk[MQK];
__device__ float  g_bias_p[C_];

// ---------------- K0: fold BN into weights, split fp32 -> fp16 hi + lo -----
// fp16 split carries ~22 mantissa bits: |w - hi - lo| <= 2^-22 |w| -> fp32-level
// accuracy through the HMMA path (binary activations make products exact).
__global__ void prep_weights(
    const float* __restrict__ qw, const float* __restrict__ qg, const float* __restrict__ qb,
    const float* __restrict__ qm, const float* __restrict__ qv,
    const float* __restrict__ kw, const float* __restrict__ kg, const float* __restrict__ kb,
    const float* __restrict__ km, const float* __restrict__ kv,
    const float* __restrict__ pw, const float* __restrict__ pbias, const float* __restrict__ pg,
    const float* __restrict__ pbeta, const float* __restrict__ pm, const float* __restrict__ pv)
{
    int idx = blockIdx.x * blockDim.x + threadIdx.x;
    if (idx < MQK * C_) {
        int d = idx / C_, c = idx % C_;
        float w, inv;
        if (d < C_) {
            inv = qg[d] / sqrtf(qv[d] + 1e-5f);
            w = qw[d * C_ + c] * inv;
        } else {
            int dd = d - C_;
            inv = kg[dd] / sqrtf(kv[dd] + 1e-5f);
            w = kw[dd * C_ + c] * inv;
        }
        __half hi = __float2half(w);
        g_Wqk_hi[idx] = hi;
        g_Wqk_lo[idx] = __float2half(w - __half2float(hi));
    }
    if (idx < C_ * C_) {
        int d = idx / C_;
        float inv = pg[d] / sqrtf(pv[d] + 1e-5f);
        float w = pw[idx] * inv;
        __half hi = __float2half(w);
        g_Wp_hi[idx] = hi;
        g_Wp_lo[idx] = __float2half(w - __half2float(hi));
    }
    if (idx < MQK) {
        float inv, bias;
        if (idx < C_) {
            inv = qg[idx] / sqrtf(qv[idx] + 1e-5f);
            bias = qb[idx] - qm[idx] * inv;
        } else {
            int d = idx - C_;
            inv = kg[d] / sqrtf(kv[d] + 1e-5f);
            bias = kb[d] - km[d] * inv;
        }
        g_bias_qk[idx] = bias;
    }
    if (idx < C_) {
        float inv = pg[idx] / sqrtf(pv[idx] + 1e-5f);
        g_bias_p[idx] = pbias[idx] * inv + pbeta[idx] - pm[idx] * inv;
    }
}

// ---------------- K1: multi-step LIF over raw input -> binary spikes -------
__global__ void lif_input(const float* __restrict__ x, __half* __restrict__ s)
{
    int j = blockIdx.x * blockDim.x + threadIdx.x;
    if (j >= BCN) return;
    float v = 0.0f;
#pragma unroll
    for (int t = 0; t < T_; ++t) {
        v = 0.5f * v + x[t * BCN + j];
        if (v >= 1.0f) {
            s[t * BCN + j] = __float2half(1.0f);
            v = 0.0f;
        } else {
            s[t * BCN + j] = __float2half(0.0f);
        }
    }
}

// ---------------- K2/K4: pipelined split-precision fp16 GEMM ---------------
// Out[z] = (A_hi + A_lo) @ B[z] + bias, fp32 accumulate/output.
// A: M x K_ row-major (shared across batch, L2-resident). B[z]: K_ x N_ row-major.
// cp.async 2-stage double buffer, BK=64 (6 k-iters).
#define BM 128
#define BN 128
#define BK 64
#define SA_STRIDE (BK + 8)    // 72 halfs (144 B, 16B-aligned rows)
#define SB_STRIDE (BN + 8)    // 136 halfs (272 B)
#define STAGE_HALFS (2 * BM * SA_STRIDE + BK * SB_STRIDE)  // 27136
#define GEMM_SMEM (2 * STAGE_HALFS * 2)                    // 108544 bytes

__device__ __forceinline__ void cp_async16(__half* smem_dst, const __half* gmem_src)
{
    unsigned saddr = (unsigned)__cvta_generic_to_shared(smem_dst);
    asm volatile("cp.async.cg.shared.global [%0], [%1], 16;\n" :: "r"(saddr), "l"(gmem_src));
}

__global__ __launch_bounds__(256) void gemm_split(
    const __half* __restrict__ A_hi,
    const __half* __restrict__ A_lo,
    const __half* __restrict__ Bmat,
    const float* __restrict__ bias,
    float* __restrict__ Out,
    int M)
{
    extern __shared__ char smem[];
    __half* sbase = (__half*)smem;
    float* stage_f = (float*)smem;    // epilogue reuse (64 KB)

    const int z     = blockIdx.z;
    const int tileM = blockIdx.y * BM;
    const int tileN = blockIdx.x * BN;
    const __half* Bz = Bmat + (size_t)z * K_ * N_;
    float* Oz = Out + (size_t)z * M * N_;

    const int tid  = threadIdx.x;
    const int warp = tid >> 5;
    const int wm   = warp & 1;   // 2 warps along M (64 rows each)
    const int wn   = warp >> 1;  // 4 warps along N (32 cols each)

    wmma::fragment<wmma::accumulator, 16, 16, 16, float> c[4][2];
#pragma unroll
    for (int i = 0; i < 4; i++)
#pragma unroll
        for (int j = 0; j < 2; j++) wmma::fill_fragment(c[i][j], 0.0f);

    constexpr int NITER = K_ / BK;  // 6

    // ---- async stage loader: 3072 x 16B per stage, 12 per thread ----
    auto load_stage = [&](int st, int k0) {
        __half* dA_hi = sbase + st * STAGE_HALFS;
        __half* dA_lo = dA_hi + BM * SA_STRIDE;
        __half* dB    = dA_hi + 2 * BM * SA_STRIDE;
#pragma unroll
        for (int i = 0; i < 4; i++) {
            int v  = tid + i * 256;      // 0..1023
            int r  = v >> 3;             // A row 0..127
            int ck = (v & 7) << 3;       // A col by 8
            cp_async16(dA_hi + r * SA_STRIDE + ck,
                       A_hi + (size_t)(tileM + r) * K_ + k0 + ck);
            cp_async16(dA_lo + r * SA_STRIDE + ck,
                       A_lo + (size_t)(tileM + r) * K_ + k0 + ck);
        }
#pragma unroll
        for (int i = 0; i < 4; i++) {
            int v  = tid + i * 256;
            int r  = v >> 4;             // B row 0..63
            int cn = (v & 15) << 3;      // B col by 8
            cp_async16(dB + r * SB_STRIDE + cn,
                       Bz + (size_t)(k0 + r) * N_ + tileN + cn);
        }
    };

    load_stage(0, 0);
    asm volatile("cp.async.commit_group;\n");

#pragma unroll
    for (int it = 0; it < NITER; ++it) {
        if (it + 1 < NITER) {
            load_stage((it + 1) & 1, (it + 1) * BK);
            asm volatile("cp.async.commit_group;\n");
            asm volatile("cp.async.wait_group 1;\n");
        } else {
            asm volatile("cp.async.wait_group 0;\n");
        }
        __syncthreads();

        const __half* cA_hi = sbase + (it & 1) * STAGE_HALFS;
        const __half* cA_lo = cA_hi + BM * SA_STRIDE;
        const __half* cB    = cA_hi + 2 * BM * SA_STRIDE;

#pragma unroll
        for (int kk = 0; kk < BK / 16; ++kk) {
            wmma::fragment<wmma::matrix_b, 16, 16, 16, __half, wmma::row_major> bfr[2];
#pragma unroll
            for (int j = 0; j < 2; j++)
                wmma::load_matrix_sync(bfr[j], cB + kk * 16 * SB_STRIDE + wn * 32 + j * 16, SB_STRIDE);
            wmma::fragment<wmma::matrix_a, 16, 16, 16, __half, wmma::row_major> afr;
#pragma unroll
            for (int i = 0; i < 4; i++) {
                wmma::load_matrix_sync(afr, cA_hi + (wm * 64 + i * 16) * SA_STRIDE + kk * 16, SA_STRIDE);
#pragma unroll
                for (int j = 0; j < 2; j++) wmma::mma_sync(c[i][j], afr, bfr[j], c[i][j]);
                wmma::load_matrix_sync(afr, cA_lo + (wm * 64 + i * 16) * SA_STRIDE + kk * 16, SA_STRIDE);
#pragma unroll
                for (int j = 0; j < 2; j++) wmma::mma_sync(c[i][j], afr, bfr[j], c[i][j]);
            }
        }
        __syncthreads();
    }

    // epilogue: stage accumulators in smem, add per-row bias, coalesced write
#pragma unroll
    for (int i = 0; i < 4; i++)
#pragma unroll
        for (int j = 0; j < 2; j++)
            wmma::store_matrix_sync(stage_f + (wm * 64 + i * 16) * BN + wn * 32 + j * 16,
                                    c[i][j], BN, wmma::mem_row_major);
    __syncthreads();
#pragma unroll
    for (int v0 = 0; v0 < 16; ++v0) {
        int v  = tid + v0 * 256;       // 0..4095
        int m  = v >> 5;               // row in tile
        int n4 = (v & 31) << 2;        // col (float4)
        float4 val = *(float4*)(stage_f + m * BN + n4);
        float bb = bias[tileM + m];
        val.x += bb; val.y += bb; val.z += bb; val.w += bb;
        *(float4*)(Oz + (size_t)(tileM + m) * N_ + tileN + n4) = val;
    }
}

// ---------------- K3: q/k LIF + mems closed form + attn gate + y = attn*k --
// Parallelized: block = (b, head, 32-n chunk); 8 warp-groups x 6 dh channels.
// Only the scalar per-(n,t) spike-count S needs a cross-group reduction (smem);
// each thread keeps the k-spike bits for its own 6 channels and writes them.
__global__ __launch_bounds__(256) void spike_attn(
    const float* __restrict__ qk,
    const float* __restrict__ alpha_p,
    __half* __restrict__ y)
{
    __shared__ float sS[8][T_][32];

    const int blk = blockIdx.x;
    const int n0  = (blk & 7) << 5;          // 8 chunks of 32 n
    const int hh  = (blk >> 3) & (HEADS_ - 1);
    const int b   = blk >> 6;
    const int tid  = threadIdx.x;
    const int g    = tid >> 5;               // dh group 0..7 (one warp each)
    const int nloc = tid & 31;
    const int n    = n0 + nloc;
    const int rowq = hh * DH_ + g * 6;       // first of this thread's 6 dh rows
    const float alpha = *alpha_p;

    float S[T_] = {0.f, 0.f, 0.f, 0.f};
    unsigned int kb[T_] = {0u, 0u, 0u, 0u};

#pragma unroll
    for (int d = 0; d < 6; ++d) {
        float vq = 0.f, vk = 0.f;
#pragma unroll
        for (int t = 0; t < T_; ++t) {
            size_t base = (size_t)(t * B_ + b) * MQK;
            float qv = qk[(base + rowq + d) * N_ + n];
            vq = 0.5f * vq + qv;
            if (vq >= 1.0f) { S[t] += 1.0f; vq = 0.f; }
            float kv = qk[(base + C_ + rowq + d) * N_ + n];
            vk = 0.5f * vk + kv;
            if (vk >= 1.0f) { kb[t] |= (1u << d); vk = 0.f; }
        }
    }

#pragma unroll
    for (int t = 0; t < T_; ++t) sS[g][t][nloc] = S[t];
    __syncthreads();

    float St[T_];
#pragma unroll
    for (int t = 0; t < T_; ++t) {
        float acc = 0.f;
#pragma unroll
        for (int gg = 0; gg < 8; ++gg) acc += sS[gg][t][nloc];
        St[t] = acc;
    }

    const float om = 1.0f - alpha;
    float m2 = alpha * St[0] + om * St[1];
    float qs[T_];
    qs[0] = St[0] + St[0];
    qs[1] = St[0] + St[1];
    qs[2] = m2 + St[2];
    qs[3] = alpha * m2 + om * St[2] + St[3];

    const __half one  = __float2half(1.0f);
    const __half zero = __float2half(0.0f);
    float v = 0.f;
#pragma unroll
    for (int t = 0; t < T_; ++t) {
        v = 0.5f * v + qs[t];
        unsigned int mask = 0u;
        if (v >= 0.5f) { mask = kb[t]; v = 0.f; }
        size_t base = ((size_t)(t * B_ + b) * C_ + rowq) * N_ + n;
#pragma unroll
        for (int d = 0; d < 6; ++d)
            y[base + (size_t)d * N_] = ((mask >> d) & 1u) ? one : zero;
    }
}

// ---------------- launch ---------------------------------------------------
extern "C" void kernel_launch(void* const* d_in, const int* in_sizes, int n_in,
                              void* d_out, int out_size)
{
    (void)in_sizes; (void)n_in; (void)out_size;
    const float* x       = (const float*)d_in[0];
    const float* q_w     = (const float*)d_in[1];
    const float* q_gamma = (const float*)d_in[2];
    const float* q_beta  = (const float*)d_in[3];
    const float* q_mean  = (const float*)d_in[4];
    const float* q_var   = (const float*)d_in[5];
    const float* k_w     = (const float*)d_in[6];
    const float* k_gamma = (const float*)d_in[7];
    const float* k_beta  = (const float*)d_in[8];
    const float* k_mean  = (const float*)d_in[9];
    const float* k_var   = (const float*)d_in[10];
    const float* proj_w  = (const float*)d_in[11];
    const float* proj_b  = (const float*)d_in[12];
    const float* proj_g  = (const float*)d_in[13];
    const float* proj_be = (const float*)d_in[14];
    const float* proj_m  = (const float*)d_in[15];
    const float* proj_v  = (const float*)d_in[16];
    const float* m_alpha = (const float*)d_in[17];
    float* out = (float*)d_out;

    // device addresses of scratch symbols (no allocation; capture-safe)
    __half *s_p, *y_p, *wqk_hi, *wqk_lo, *wp_hi, *wp_lo;
    float *qk_p, *bias_qk, *bias_p;
    cudaGetSymbolAddress((void**)&s_p,     g_s);
    cudaGetSymbolAddress((void**)&y_p,     g_y);
    cudaGetSymbolAddress((void**)&wqk_hi,  g_Wqk_hi);
    cudaGetSymbolAddress((void**)&wqk_lo,  g_Wqk_lo);
    cudaGetSymbolAddress((void**)&wp_hi,   g_Wp_hi);
    cudaGetSymbolAddress((void**)&wp_lo,   g_Wp_lo);
    cudaGetSymbolAddress((void**)&qk_p,    g_qk);
    cudaGetSymbolAddress((void**)&bias_qk, g_bias_qk);
    cudaGetSymbolAddress((void**)&bias_p,  g_bias_p);

    cudaFuncSetAttribute(gemm_split, cudaFuncAttributeMaxDynamicSharedMemorySize, GEMM_SMEM);

    // K0: weight prep (BN fold + fp16 hi/lo split)
    prep_weights<<<(MQK * C_) / 256, 256>>>(q_w, q_gamma, q_beta, q_mean, q_var,
                                            k_w, k_gamma, k_beta, k_mean, k_var,
                                            proj_w, proj_b, proj_g, proj_be, proj_m, proj_v);
    // K1: LIF(x) -> s
    lif_input<<<BCN / 256, 256>>>(x, s_p);
    // K2: qk_bn = [Wq';Wk'] @ s + bias  (split fp16, fp32 acc, pipelined)
    gemm_split<<<dim3(N_ / BN, MQK / BM, T_ * B_), 256, GEMM_SMEM>>>(
        wqk_hi, wqk_lo, s_p, bias_qk, qk_p, MQK);
    // K3: q/k LIF + mems + attn gate -> y (binary)
    spike_attn<<<B_ * HEADS_ * (N_ / 32), 256>>>(qk_p, m_alpha, y_p);
    // K4: out = Wp' @ y + bias_p
    gemm_split<<<dim3(N_ / BN, C_ / BM, T_ * B_), 256, GEMM_SMEM>>>(
        wp_hi, wp_lo, y_p, bias_p, out, C_);
}

// round 7
// speedup vs baseline: 1.2173x; 1.2085x over previous
#include <cuda_runtime.h>
#include <cuda_fp16.h>
#include <mma.h>

using namespace nvcuda;

#define T_ 4
#define B_ 32
#define C_ 384
#define N_ 256
#define HEADS_ 8
#define DH_ 48
#define MQK 768   // q rows [0,384) and k rows [384,768) stacked
#define K_ 384    // GEMM inner dim (both GEMMs)

static constexpr int BCN  = B_ * C_ * N_;        // 3,145,728
static constexpr int TBCN = T_ * BCN;            // 12,582,912

// ---------------- scratch (static device memory; no cudaMalloc allowed) ----
__device__ __half g_s[TBCN];                          // LIF(x) spikes, binary [z][c][n]
__device__ float  g_qk[(size_t)T_ * B_ * MQK * N_];   // BN(conv(s)) for q&k
__device__ __half g_y[TBCN];                          // attn*k, binary [z][c][n]
__device__ __half g_Wqk_hi[MQK * K_];
__device__ __half g_Wqk_lo[MQK * K_];
__device__ __half g_Wp_hi[C_ * K_];                   // proj: hi-only (error ~1.4e-4)
__device__ float  g_bias_qk[MQK];
__device__ float  g_bias_p[C_];

// ---------------- K0: fold BN into weights, split fp32 -> fp16 hi (+ lo) ---
// q/k weights get the full hi+lo split (22 mantissa bits -> exact spike
// decisions). proj weights are hi-only: downstream is linear, rounding noise
// ~1.4e-4 rel (calibrated against the measured bf16 run at 8x this error).
__global__ void prep_weights(
    const float* __restrict__ qw, const float* __restrict__ qg, const float* __restrict__ qb,
    const float* __restrict__ qm, const float* __restrict__ qv,
    const float* __restrict__ kw, const float* __restrict__ kg, const float* __restrict__ kb,
    const float* __restrict__ km, const float* __restrict__ kv,
    const float* __restrict__ pw, const float* __restrict__ pbias, const float* __restrict__ pg,
    const float* __restrict__ pbeta, const float* __restrict__ pm, const float* __restrict__ pv)
{
    int idx = blockIdx.x * blockDim.x + threadIdx.x;
    if (idx < MQK * K_) {
        int d = idx / K_, c = idx % K_;
        float w, inv;
        if (d < C_) {
            inv = qg[d] / sqrtf(qv[d] + 1e-5f);
            w = qw[d * C_ + c] * inv;
        } else {
            int dd = d - C_;
            inv = kg[dd] / sqrtf(kv[dd] + 1e-5f);
            w = kw[dd * C_ + c] * inv;
        }
        __half hi = __float2half(w);
        g_Wqk_hi[idx] = hi;
        g_Wqk_lo[idx] = __float2half(w - __half2float(hi));
    }
    if (idx < C_ * K_) {
        int d = idx / K_;
        float inv = pg[d] / sqrtf(pv[d] + 1e-5f);
        g_Wp_hi[idx] = __float2half(pw[idx] * inv);
    }
    if (idx < MQK) {
        float inv, bias;
        if (idx < C_) {
            inv = qg[idx] / sqrtf(qv[idx] + 1e-5f);
            bias = qb[idx] - qm[idx] * inv;
        } else {
            int d = idx - C_;
            inv = kg[d] / sqrtf(kv[d] + 1e-5f);
            bias = kb[d] - km[d] * inv;
        }
        g_bias_qk[idx] = bias;
    }
    if (idx < C_) {
        float inv = pg[idx] / sqrtf(pv[idx] + 1e-5f);
        g_bias_p[idx] = pbias[idx] * inv + pbeta[idx] - pm[idx] * inv;
    }
}

// ---------------- K1: multi-step LIF over raw input -> binary spikes -------
__global__ void lif_input(const float* __restrict__ x, __half* __restrict__ s)
{
    int j = blockIdx.x * blockDim.x + threadIdx.x;
    if (j >= BCN) return;
    float v = 0.0f;
#pragma unroll
    for (int t = 0; t < T_; ++t) {
        v = 0.5f * v + x[t * BCN + j];
        if (v >= 1.0f) {
            s[t * BCN + j] = __float2half(1.0f);
            v = 0.0f;
        } else {
            s[t * BCN + j] = __float2half(0.0f);
        }
    }
}

// ---------------- K2/K4: wmma GEMM, optional fp16 hi/lo split --------------
// Out[z] = (A_hi [+ A_lo]) @ B[z] + bias, fp32 accumulate/output.
// A: M x K_ row-major (shared across batch, L2-resident). B[z]: K_ x N_ row-major.
// Warp grid 4(M) x 2(N): warp tile 32x64 -> smem read traffic 48KB/iter
// (vs 80KB for the 2x4 grid). Epilogue stages 64 rows at a time (32KB smem).
#define BM 128
#define BN 128
#define BK 32
#define SA_STRIDE (BK + 8)   // 40 halfs
#define SB_STRIDE (BN + 8)   // 136 halfs
#define GEMM_SMEM 32768      // epilogue staging 64x128 fp32 dominates

template<bool SPLIT>
__global__ __launch_bounds__(256) void gemm_ws(
    const __half* __restrict__ A_hi,
    const __half* __restrict__ A_lo,
    const __half* __restrict__ Bmat,
    const float* __restrict__ bias,
    float* __restrict__ Out,
    int M)
{
    extern __shared__ char smem[];
    __half* sA_hi = (__half*)smem;                                   // 10240 B
    __half* sA_lo = sA_hi + BM * SA_STRIDE;                          // 10240 B (SPLIT only)
    __half* sB    = SPLIT ? (sA_lo + BM * SA_STRIDE) : sA_lo;        // 8704 B
    float* stage  = (float*)smem;                                    // epilogue reuse 32 KB

    const int z     = blockIdx.z;
    const int tileM = blockIdx.y * BM;
    const int tileN = blockIdx.x * BN;
    const __half* Bz = Bmat + (size_t)z * K_ * N_;
    float* Oz = Out + (size_t)z * M * N_;

    const int tid  = threadIdx.x;
    const int warp = tid >> 5;
    const int wm   = warp & 3;    // 4 warps along M (32 rows each)
    const int wn   = warp >> 2;   // 2 warps along N (64 cols each)

    wmma::fragment<wmma::accumulator, 16, 16, 16, float> c[2][4];
#pragma unroll
    for (int i = 0; i < 2; i++)
#pragma unroll
        for (int j = 0; j < 4; j++) wmma::fill_fragment(c[i][j], 0.0f);

    for (int k0 = 0; k0 < K_; k0 += BK) {
        // A tiles: 128x32 halfs = 512 uint4 each -> 2 per thread
#pragma unroll
        for (int i = 0; i < 2; i++) {
            int v  = tid + i * 256;
            int r  = v >> 2;
            int ck = (v & 3) << 3;
            *(uint4*)(sA_hi + r * SA_STRIDE + ck) =
                *(const uint4*)(A_hi + (size_t)(tileM + r) * K_ + k0 + ck);
            if (SPLIT)
                *(uint4*)(sA_lo + r * SA_STRIDE + ck) =
                    *(const uint4*)(A_lo + (size_t)(tileM + r) * K_ + k0 + ck);
        }
        // B tile: 32x128 halfs = 512 uint4
#pragma unroll
        for (int i = 0; i < 2; i++) {
            int v  = tid + i * 256;
            int r  = v >> 4;
            int cn = (v & 15) << 3;
            *(uint4*)(sB + r * SB_STRIDE + cn) =
                *(const uint4*)(Bz + (size_t)(k0 + r) * N_ + tileN + cn);
        }
        __syncthreads();

#pragma unroll
        for (int kk = 0; kk < 2; ++kk) {
            wmma::fragment<wmma::matrix_b, 16, 16, 16, __half, wmma::row_major> bfr[4];
#pragma unroll
            for (int j = 0; j < 4; j++)
                wmma::load_matrix_sync(bfr[j], sB + kk * 16 * SB_STRIDE + wn * 64 + j * 16, SB_STRIDE);
            wmma::fragment<wmma::matrix_a, 16, 16, 16, __half, wmma::row_major> afr;
#pragma unroll
            for (int i = 0; i < 2; i++) {
                wmma::load_matrix_sync(afr, sA_hi + (wm * 32 + i * 16) * SA_STRIDE + kk * 16, SA_STRIDE);
#pragma unroll
                for (int j = 0; j < 4; j++) wmma::mma_sync(c[i][j], afr, bfr[j], c[i][j]);
                if (SPLIT) {
                    wmma::load_matrix_sync(afr, sA_lo + (wm * 32 + i * 16) * SA_STRIDE + kk * 16, SA_STRIDE);
#pragma unroll
                    for (int j = 0; j < 4; j++) wmma::mma_sync(c[i][j], afr, bfr[j], c[i][j]);
                }
            }
        }
        __syncthreads();
    }

    // epilogue: two 64-row rounds through 32KB smem staging, +bias, coalesced
#pragma unroll
    for (int rnd = 0; rnd < 2; ++rnd) {
        if ((wm >> 1) == rnd) {
#pragma unroll
            for (int i = 0; i < 2; i++)
#pragma unroll
                for (int j = 0; j < 4; j++)
                    wmma::store_matrix_sync(stage + ((wm & 1) * 32 + i * 16) * BN + wn * 64 + j * 16,
                                            c[i][j], BN, wmma::mem_row_major);
        }
        __syncthreads();
#pragma unroll
        for (int q = 0; q < 8; ++q) {
            int v  = tid + q * 256;        // 0..2047
            int m  = v >> 5;               // row 0..63
            int n4 = (v & 31) << 2;        // col (float4)
            float4 val = *(float4*)(stage + m * BN + n4);
            float bb = bias[tileM + rnd * 64 + m];
            val.x += bb; val.y += bb; val.z += bb; val.w += bb;
            *(float4*)(Oz + (size_t)(tileM + rnd * 64 + m) * N_ + tileN + n4) = val;
        }
        __syncthreads();
    }
}

// ---------------- K3: q/k LIF + mems closed form + attn gate + y = attn*k --
// block = (b, head, 32-n chunk); 8 warp-groups x 6 dh channels. Per-(n,t)
// spike-count S reduced through smem; k-spike bits stay thread-local.
__global__ __launch_bounds__(256) void spike_attn(
    const float* __restrict__ qk,
    const float* __restrict__ alpha_p,
    __half* __restrict__ y)
{
    __shared__ float sS[8][T_][32];

    const int blk = blockIdx.x;
    const int n0  = (blk & 7) << 5;
    const int hh  = (blk >> 3) & (HEADS_ - 1);
    const int b   = blk >> 6;
    const int tid  = threadIdx.x;
    const int g    = tid >> 5;
    const int nloc = tid & 31;
    const int n    = n0 + nloc;
    const int rowq = hh * DH_ + g * 6;
    const float alpha = *alpha_p;

    float S[T_] = {0.f, 0.f, 0.f, 0.f};
    unsigned int kb[T_] = {0u, 0u, 0u, 0u};

#pragma unroll
    for (int d = 0; d < 6; ++d) {
        float vq = 0.f, vk = 0.f;
#pragma unroll
        for (int t = 0; t < T_; ++t) {
            size_t base = (size_t)(t * B_ + b) * MQK;
            float qv = qk[(base + rowq + d) * N_ + n];
            vq = 0.5f * vq + qv;
            if (vq >= 1.0f) { S[t] += 1.0f; vq = 0.f; }
            float kv = qk[(base + C_ + rowq + d) * N_ + n];
            vk = 0.5f * vk + kv;
            if (vk >= 1.0f) { kb[t] |= (1u << d); vk = 0.f; }
        }
    }

#pragma unroll
    for (int t = 0; t < T_; ++t) sS[g][t][nloc] = S[t];
    __syncthreads();

    float St[T_];
#pragma unroll
    for (int t = 0; t < T_; ++t) {
        float acc = 0.f;
#pragma unroll
        for (int gg = 0; gg < 8; ++gg) acc += sS[gg][t][nloc];
        St[t] = acc;
    }

    const float om = 1.0f - alpha;
    float m2 = alpha * St[0] + om * St[1];
    float qs[T_];
    qs[0] = St[0] + St[0];
    qs[1] = St[0] + St[1];
    qs[2] = m2 + St[2];
    qs[3] = alpha * m2 + om * St[2] + St[3];

    const __half one  = __float2half(1.0f);
    const __half zero = __float2half(0.0f);
    float v = 0.f;
#pragma unroll
    for (int t = 0; t < T_; ++t) {
        v = 0.5f * v + qs[t];
        unsigned int mask = 0u;
        if (v >= 0.5f) { mask = kb[t]; v = 0.f; }
        size_t base = ((size_t)(t * B_ + b) * C_ + rowq) * N_ + n;
#pragma unroll
        for (int d = 0; d < 6; ++d)
            y[base + (size_t)d * N_] = ((mask >> d) & 1u) ? one : zero;
    }
}

// ---------------- launch ---------------------------------------------------
extern "C" void kernel_launch(void* const* d_in, const int* in_sizes, int n_in,
                              void* d_out, int out_size)
{
    (void)in_sizes; (void)n_in; (void)out_size;
    const float* x       = (const float*)d_in[0];
    const float* q_w     = (const float*)d_in[1];
    const float* q_gamma = (const float*)d_in[2];
    const float* q_beta  = (const float*)d_in[3];
    const float* q_mean  = (const float*)d_in[4];
    const float* q_var   = (const float*)d_in[5];
    const float* k_w     = (const float*)d_in[6];
    const float* k_gamma = (const float*)d_in[7];
    const float* k_beta  = (const float*)d_in[8];
    const float* k_mean  = (const float*)d_in[9];
    const float* k_var   = (const float*)d_in[10];
    const float* proj_w  = (const float*)d_in[11];
    const float* proj_b  = (const float*)d_in[12];
    const float* proj_g  = (const float*)d_in[13];
    const float* proj_be = (const float*)d_in[14];
    const float* proj_m  = (const float*)d_in[15];
    const float* proj_v  = (const float*)d_in[16];
    const float* m_alpha = (const float*)d_in[17];
    float* out = (float*)d_out;

    __half *s_p, *y_p, *wqk_hi, *wqk_lo, *wp_hi;
    float *qk_p, *bias_qk, *bias_p;
    cudaGetSymbolAddress((void**)&s_p,     g_s);
    cudaGetSymbolAddress((void**)&y_p,     g_y);
    cudaGetSymbolAddress((void**)&wqk_hi,  g_Wqk_hi);
    cudaGetSymbolAddress((void**)&wqk_lo,  g_Wqk_lo);
    cudaGetSymbolAddress((void**)&wp_hi,   g_Wp_hi);
    cudaGetSymbolAddress((void**)&qk_p,    g_qk);
    cudaGetSymbolAddress((void**)&bias_qk, g_bias_qk);
    cudaGetSymbolAddress((void**)&bias_p,  g_bias_p);

    cudaFuncSetAttribute(gemm_ws<true>,  cudaFuncAttributeMaxDynamicSharedMemorySize, GEMM_SMEM);
    cudaFuncSetAttribute(gemm_ws<false>, cudaFuncAttributeMaxDynamicSharedMemorySize, GEMM_SMEM);

    // K0: weight prep (BN fold + fp16 hi/lo split; proj hi-only)
    prep_weights<<<(MQK * K_) / 256, 256>>>(q_w, q_gamma, q_beta, q_mean, q_var,
                                            k_w, k_gamma, k_beta, k_mean, k_var,
                                            proj_w, proj_b, proj_g, proj_be, proj_m, proj_v);
    // K1: LIF(x) -> s
    lif_input<<<BCN / 256, 256>>>(x, s_p);
    // K2: qk = [Wq';Wk'] @ s + bias  (split fp16, fp32 acc)
    gemm_ws<true><<<dim3(N_ / BN, MQK / BM, T_ * B_), 256, GEMM_SMEM>>>(
        wqk_hi, wqk_lo, s_p, bias_qk, qk_p, MQK);
    // K3: q/k LIF + mems + attn gate -> y (binary)
    spike_attn<<<B_ * HEADS_ * (N_ / 32), 256>>>(qk_p, m_alpha, y_p);
    // K4: out = Wp' @ y + bias_p  (hi-only)
    gemm_ws<false><<<dim3(N_ / BN, C_ / BM, T_ * B_), 256, GEMM_SMEM>>>(
        wp_hi, wp_hi, y_p, bias_p, out, C_);
}

// round 8
// speedup vs baseline: 1.2528x; 1.0292x over previous
#include <cuda_runtime.h>
#include <cuda_fp16.h>
#include <mma.h>

using namespace nvcuda;

#define T_ 4
#define B_ 32
#define C_ 384
#define N_ 256
#define HEADS_ 8
#define DH_ 48
#define MQK 768   // q rows [0,384) and k rows [384,768) stacked
#define K_ 384    // GEMM inner dim (both GEMMs)
#define MARGIN 4e-3f

static constexpr int BCN  = B_ * C_ * N_;        // 3,145,728
static constexpr int TBCN = T_ * BCN;            // 12,582,912

// ---------------- scratch (static device memory; no cudaMalloc allowed) ----
__device__ __half g_s[TBCN];                          // spikes, [z][c][n] (GEMM B)
__device__ __half g_sT[TBCN];                         // spikes, [z][n][c] (repair gathers)
__device__ float  g_qk[(size_t)T_ * B_ * MQK * N_];   // hi-only BN(conv(s))
__device__ __half g_y[TBCN];                          // attn*k, binary [z][c][n]
__device__ __half g_Wqk_hi[MQK * K_];
__device__ float  g_Wqk_f32[MQK * K_];                // exact folded weights (repair)
__device__ __half g_Wp_hi[C_ * K_];                   // proj: hi-only (~1.7e-4)
__device__ float  g_bias_qk[MQK];
__device__ float  g_bias_p[C_];

// ---------------- K0: fold BN into weights -----------------------------------
__global__ void prep_weights(
    const float* __restrict__ qw, const float* __restrict__ qg, const float* __restrict__ qb,
    const float* __restrict__ qm, const float* __restrict__ qv,
    const float* __restrict__ kw, const float* __restrict__ kg, const float* __restrict__ kb,
    const float* __restrict__ km, const float* __restrict__ kv,
    const float* __restrict__ pw, const float* __restrict__ pbias, const float* __restrict__ pg,
    const float* __restrict__ pbeta, const float* __restrict__ pm, const float* __restrict__ pv)
{
    int idx = blockIdx.x * blockDim.x + threadIdx.x;
    if (idx < MQK * K_) {
        int d = idx / K_, c = idx % K_;
        float w, inv;
        if (d < C_) {
            inv = qg[d] / sqrtf(qv[d] + 1e-5f);
            w = qw[d * C_ + c] * inv;
        } else {
            int dd = d - C_;
            inv = kg[dd] / sqrtf(kv[dd] + 1e-5f);
            w = kw[dd * C_ + c] * inv;
        }
        g_Wqk_hi[idx]  = __float2half(w);
        g_Wqk_f32[idx] = w;
    }
    if (idx < C_ * K_) {
        int d = idx / K_;
        float inv = pg[d] / sqrtf(pv[d] + 1e-5f);
        g_Wp_hi[idx] = __float2half(pw[idx] * inv);
    }
    if (idx < MQK) {
        float inv, bias;
        if (idx < C_) {
            inv = qg[idx] / sqrtf(qv[idx] + 1e-5f);
            bias = qb[idx] - qm[idx] * inv;
        } else {
            int d = idx - C_;
            inv = kg[d] / sqrtf(kv[d] + 1e-5f);
            bias = kb[d] - km[d] * inv;
        }
        g_bias_qk[idx] = bias;
    }
    if (idx < C_) {
        float inv = pg[idx] / sqrtf(pv[idx] + 1e-5f);
        g_bias_p[idx] = pbias[idx] * inv + pbeta[idx] - pm[idx] * inv;
    }
}

// ---------------- K1: LIF over time -> spikes in BOTH layouts ---------------
__global__ __launch_bounds__(256) void lif_input2(
    const float* __restrict__ x, __half* __restrict__ s, __half* __restrict__ sT)
{
    __shared__ __half tile[T_][32][33];
    const int n0 = blockIdx.x * 32;
    const int c0 = blockIdx.y * 32;
    const int b  = blockIdx.z;
    const int tid = threadIdx.x;
    const int nl = tid & 31;
    const int cq = tid >> 5;    // 0..7

#pragma unroll
    for (int j = 0; j < 4; ++j) {
        const int cl = cq + j * 8;
        const int c  = c0 + cl;
        float v = 0.f;
#pragma unroll
        for (int t = 0; t < T_; ++t) {
            v = 0.5f * v + x[((size_t)(t * B_ + b) * C_ + c) * N_ + n0 + nl];
            if (v >= 1.0f) { tile[t][cl][nl] = __float2half(1.0f); v = 0.f; }
            else           { tile[t][cl][nl] = __float2half(0.0f); }
        }
    }
    __syncthreads();

    const int r2 = tid >> 3;           // 0..31
    const int q4 = (tid & 7) * 4;      // 0..28
#pragma unroll
    for (int t = 0; t < T_; ++t) {
        const size_t zb = (size_t)(t * B_ + b);
        // layout A: [z][c][n]
        {
            __half hv[4];
#pragma unroll
            for (int i = 0; i < 4; ++i) hv[i] = tile[t][r2][q4 + i];
            *(uint2*)(s + (zb * C_ + c0 + r2) * N_ + n0 + q4) = *(uint2*)hv;
        }
        // layout B: [z][n][c]
        {
            __half hv[4];
#pragma unroll
            for (int i = 0; i < 4; ++i) hv[i] = tile[t][q4 + i][r2];
            *(uint2*)(sT + (zb * N_ + n0 + r2) * C_ + c0 + q4) = *(uint2*)hv;
        }
    }
}

// ---------------- K2/K4: wmma GEMM (hi-only) --------------------------------
#define BM 128
#define BN 128
#define BK 32
#define SA_STRIDE (BK + 8)   // 40 halfs
#define SB_STRIDE (BN + 8)   // 136 halfs
#define GEMM_SMEM 32768      // epilogue staging 64x128 fp32 dominates

__global__ __launch_bounds__(256) void gemm_hi(
    const __half* __restrict__ A_hi,
    const __half* __restrict__ Bmat,
    const float* __restrict__ bias,
    float* __restrict__ Out,
    int M)
{
    extern __shared__ char smem[];
    __half* sA_hi = (__half*)smem;                   // 10240 B
    __half* sB    = sA_hi + BM * SA_STRIDE;          // 8704 B
    float* stage  = (float*)smem;                    // epilogue reuse 32 KB

    const int z     = blockIdx.z;
    const int tileM = blockIdx.y * BM;
    const int tileN = blockIdx.x * BN;
    const __half* Bz = Bmat + (size_t)z * K_ * N_;
    float* Oz = Out + (size_t)z * M * N_;

    const int tid  = threadIdx.x;
    const int warp = tid >> 5;
    const int wm   = warp & 3;    // 4 warps along M (32 rows each)
    const int wn   = warp >> 2;   // 2 warps along N (64 cols each)

    wmma::fragment<wmma::accumulator, 16, 16, 16, float> c[2][4];
#pragma unroll
    for (int i = 0; i < 2; i++)
#pragma unroll
        for (int j = 0; j < 4; j++) wmma::fill_fragment(c[i][j], 0.0f);

    for (int k0 = 0; k0 < K_; k0 += BK) {
#pragma unroll
        for (int i = 0; i < 2; i++) {
            int v  = tid + i * 256;
            int r  = v >> 2;
            int ck = (v & 3) << 3;
            *(uint4*)(sA_hi + r * SA_STRIDE + ck) =
                *(const uint4*)(A_hi + (size_t)(tileM + r) * K_ + k0 + ck);
        }
#pragma unroll
        for (int i = 0; i < 2; i++) {
            int v  = tid + i * 256;
            int r  = v >> 4;
            int cn = (v & 15) << 3;
            *(uint4*)(sB + r * SB_STRIDE + cn) =
                *(const uint4*)(Bz + (size_t)(k0 + r) * N_ + tileN + cn);
        }
        __syncthreads();

#pragma unroll
        for (int kk = 0; kk < 2; ++kk) {
            wmma::fragment<wmma::matrix_b, 16, 16, 16, __half, wmma::row_major> bfr[4];
#pragma unroll
            for (int j = 0; j < 4; j++)
                wmma::load_matrix_sync(bfr[j], sB + kk * 16 * SB_STRIDE + wn * 64 + j * 16, SB_STRIDE);
            wmma::fragment<wmma::matrix_a, 16, 16, 16, __half, wmma::row_major> afr;
#pragma unroll
            for (int i = 0; i < 2; i++) {
                wmma::load_matrix_sync(afr, sA_hi + (wm * 32 + i * 16) * SA_STRIDE + kk * 16, SA_STRIDE);
#pragma unroll
                for (int j = 0; j < 4; j++) wmma::mma_sync(c[i][j], afr, bfr[j], c[i][j]);
            }
        }
        __syncthreads();
    }

#pragma unroll
    for (int rnd = 0; rnd < 2; ++rnd) {
        if ((wm >> 1) == rnd) {
#pragma unroll
            for (int i = 0; i < 2; i++)
#pragma unroll
                for (int j = 0; j < 4; j++)
                    wmma::store_matrix_sync(stage + ((wm & 1) * 32 + i * 16) * BN + wn * 64 + j * 16,
                                            c[i][j], BN, wmma::mem_row_major);
        }
        __syncthreads();
#pragma unroll
        for (int q = 0; q < 8; ++q) {
            int v  = tid + q * 256;
            int m  = v >> 5;
            int n4 = (v & 31) << 2;
            float4 val = *(float4*)(stage + m * BN + n4);
            float bb = bias[tileM + rnd * 64 + m];
            val.x += bb; val.y += bb; val.z += bb; val.w += bb;
            *(float4*)(Oz + (size_t)(tileM + rnd * 64 + m) * N_ + tileN + n4) = val;
        }
        __syncthreads();
    }
}

// ---------------- K3: spike attn with exact threshold repair ----------------
// Phase 1: approx LIF on hi-only qk, flag chains within MARGIN of threshold.
// Phase 2: warp-cooperative exact fp32 recompute of flagged chains.
// Phase 3: exact S_t popcounts -> attn gate -> y = attn & k.
#define LISTCAP 3072

__global__ __launch_bounds__(256) void spike_attn2(
    const float* __restrict__ qk,
    const float* __restrict__ alpha_p,
    const __half* __restrict__ sT,
    const float* __restrict__ W32,
    const float* __restrict__ bias,
    __half* __restrict__ y)
{
    __shared__ unsigned char sBits[96][32];   // chains: [0,48)=q, [48,96)=k
    __shared__ unsigned short list[LISTCAP];
    __shared__ int cnt;
    __shared__ float sS[8][T_][32];

    const int blk = blockIdx.x;
    const int n0  = (blk & 7) << 5;
    const int hh  = (blk >> 3) & (HEADS_ - 1);
    const int b   = blk >> 6;
    const int tid  = threadIdx.x;
    const int g    = tid >> 5;
    const int lane = tid & 31;
    const float alpha = *alpha_p;

    if (tid == 0) cnt = 0;
    __syncthreads();

    // ---- phase 1: approx chains + flags ----
    {
        const int nloc = lane;
        const int n = n0 + nloc;
#pragma unroll
        for (int d = 0; d < 6; ++d) {
            const int dh = g * 6 + d;
#pragma unroll
            for (int side = 0; side < 2; ++side) {
                const int row = side * C_ + hh * DH_ + dh;
                float v = 0.f; unsigned bits = 0; bool flag = false;
#pragma unroll
                for (int t = 0; t < T_; ++t) {
                    float val = qk[((size_t)(t * B_ + b) * MQK + row) * N_ + n];
                    v = 0.5f * v + val;
                    if (fabsf(v - 1.0f) < MARGIN) flag = true;
                    if (v >= 1.0f) { bits |= (1u << t); v = 0.f; }
                }
                const int chain = side * 48 + dh;
                sBits[chain][nloc] = (unsigned char)bits;
                if (flag) {
                    int idx = atomicAdd(&cnt, 1);
                    if (idx < LISTCAP)
                        list[idx] = (unsigned short)((chain << 5) | nloc);
                }
            }
        }
    }
    __syncthreads();

    // ---- phase 2: exact repair (one warp per flagged chain) ----
    {
        const int m = min(cnt, LISTCAP);
        for (int e = g; e < m; e += 8) {
            const int ent   = list[e];
            const int chain = ent >> 5;
            const int nloc  = ent & 31;
            const int row   = (chain < 48) ? (hh * DH_ + chain)
                                           : (C_ + hh * DH_ + (chain - 48));
            const int n = n0 + nloc;
            const float* wrow = W32 + (size_t)row * K_;
            float v = 0.f; unsigned bits = 0;
#pragma unroll
            for (int t = 0; t < T_; ++t) {
                const __half* scol = sT + ((size_t)(t * B_ + b) * N_ + n) * C_;
                float part = 0.f;
#pragma unroll
                for (int c = 0; c < K_ / 32; ++c) {
                    int cc = lane + c * 32;
                    part += wrow[cc] * __half2float(scol[cc]);
                }
#pragma unroll
                for (int o = 16; o; o >>= 1)
                    part += __shfl_xor_sync(0xFFFFFFFFu, part, o);
                float val = part + bias[row];
                v = 0.5f * v + val;
                if (v >= 1.0f) { bits |= (1u << t); v = 0.f; }
            }
            if (lane == 0) sBits[chain][nloc] = (unsigned char)bits;
        }
    }
    __syncthreads();

    // ---- phase 3: exact popcounts -> attn -> y ----
    const int nloc = lane;
    const int n = n0 + nloc;
    float S[T_] = {0.f, 0.f, 0.f, 0.f};
    unsigned kbyte[6];
#pragma unroll
    for (int d = 0; d < 6; ++d) {
        unsigned qb = sBits[g * 6 + d][nloc];
        kbyte[d]    = sBits[48 + g * 6 + d][nloc];
#pragma unroll
        for (int t = 0; t < T_; ++t) S[t] += (float)((qb >> t) & 1u);
    }
#pragma unroll
    for (int t = 0; t < T_; ++t) sS[g][t][nloc] = S[t];
    __syncthreads();

    float St[T_];
#pragma unroll
    for (int t = 0; t < T_; ++t) {
        float acc = 0.f;
#pragma unroll
        for (int gg = 0; gg < 8; ++gg) acc += sS[gg][t][nloc];
        St[t] = acc;
    }

    const float om = 1.0f - alpha;
    float m2 = alpha * St[0] + om * St[1];
    float qs[T_];
    qs[0] = St[0] + St[0];
    qs[1] = St[0] + St[1];
    qs[2] = m2 + St[2];
    qs[3] = alpha * m2 + om * St[2] + St[3];

    const __half one  = __float2half(1.0f);
    const __half zero = __float2half(0.0f);
    const int rowq = hh * DH_ + g * 6;
    float v = 0.f;
#pragma unroll
    for (int t = 0; t < T_; ++t) {
        v = 0.5f * v + qs[t];
        bool fire = false;
        if (v >= 0.5f) { fire = true; v = 0.f; }
        size_t base = ((size_t)(t * B_ + b) * C_ + rowq) * N_ + n;
#pragma unroll
        for (int d = 0; d < 6; ++d)
            y[base + (size_t)d * N_] = (fire && ((kbyte[d] >> t) & 1u)) ? one : zero;
    }
}

// ---------------- launch ---------------------------------------------------
extern "C" void kernel_launch(void* const* d_in, const int* in_sizes, int n_in,
                              void* d_out, int out_size)
{
    (void)in_sizes; (void)n_in; (void)out_size;
    const float* x       = (const float*)d_in[0];
    const float* q_w     = (const float*)d_in[1];
    const float* q_gamma = (const float*)d_in[2];
    const float* q_beta  = (const float*)d_in[3];
    const float* q_mean  = (const float*)d_in[4];
    const float* q_var   = (const float*)d_in[5];
    const float* k_w     = (const float*)d_in[6];
    const float* k_gamma = (const float*)d_in[7];
    const float* k_beta  = (const float*)d_in[8];
    const float* k_mean  = (const float*)d_in[9];
    const float* k_var   = (const float*)d_in[10];
    const float* proj_w  = (const float*)d_in[11];
    const float* proj_b  = (const float*)d_in[12];
    const float* proj_g  = (const float*)d_in[13];
    const float* proj_be = (const float*)d_in[14];
    const float* proj_m  = (const float*)d_in[15];
    const float* proj_v  = (const float*)d_in[16];
    const float* m_alpha = (const float*)d_in[17];
    float* out = (float*)d_out;

    __half *s_p, *sT_p, *y_p, *wqk_hi, *wp_hi;
    float *qk_p, *bias_qk, *bias_p, *w32_p;
    cudaGetSymbolAddress((void**)&s_p,     g_s);
    cudaGetSymbolAddress((void**)&sT_p,    g_sT);
    cudaGetSymbolAddress((void**)&y_p,     g_y);
    cudaGetSymbolAddress((void**)&wqk_hi,  g_Wqk_hi);
    cudaGetSymbolAddress((void**)&w32_p,   g_Wqk_f32);
    cudaGetSymbolAddress((void**)&wp_hi,   g_Wp_hi);
    cudaGetSymbolAddress((void**)&qk_p,    g_qk);
    cudaGetSymbolAddress((void**)&bias_qk, g_bias_qk);
    cudaGetSymbolAddress((void**)&bias_p,  g_bias_p);

    cudaFuncSetAttribute(gemm_hi, cudaFuncAttributeMaxDynamicSharedMemorySize, GEMM_SMEM);

    // K0: weight prep (BN fold; q/k hi + exact fp32; proj hi-only)
    prep_weights<<<(MQK * K_) / 256, 256>>>(q_w, q_gamma, q_beta, q_mean, q_var,
                                            k_w, k_gamma, k_beta, k_mean, k_var,
                                            proj_w, proj_b, proj_g, proj_be, proj_m, proj_v);
    // K1: LIF(x) -> s ([z][c][n]) and sT ([z][n][c])
    lif_input2<<<dim3(N_ / 32, C_ / 32, B_), 256>>>(x, s_p, sT_p);
    // K2: qk = [Wq';Wk']_hi @ s + bias  (hi-only; repaired in K3)
    gemm_hi<<<dim3(N_ / BN, MQK / BM, T_ * B_), 256, GEMM_SMEM>>>(
        wqk_hi, s_p, bias_qk, qk_p, MQK);
    // K3: approx spikes + exact threshold repair + attn gate -> y
    spike_attn2<<<B_ * HEADS_ * (N_ / 32), 256>>>(qk_p, m_alpha, sT_p, w32_p, bias_qk, y_p);
    // K4: out = Wp'_hi @ y + bias_p
    gemm_hi<<<dim3(N_ / BN, C_ / BM, T_ * B_), 256, GEMM_SMEM>>>(
        wp_hi, y_p, bias_p, out, C_);
}